// round 1
// baseline (speedup 1.0000x reference)
#include <cuda_runtime.h>
#include <math.h>

// rbfLayer: continuous conv with separable radial/angular linear RBF basis.
// Out[p,i] = sum_{e in p} sum_{n,m,j} K[i,j,n,m] * c_e[n]*f_e[m] * feat[nbr_e, j]
// Factorized: Z_p[nm,j] = sum_e a_e[nm]*fv_e[j]  (accumulated over edges),
//             Out[p,i]  = sum_{nm,j} K[i,j,nm] * Z_p[nm,j].
//
// 4 lanes per point. Lane t owns radial basis n = t (4 nm slots -> Z[4][8] regs).

#define FIN  8
#define FOUT 8
#define NBASIS 4
#define MBASIS 4
#define LANES_PER_PT 4
#define PTS_PER_BLOCK 32
#define BLOCK_THREADS (PTS_PER_BLOCK * LANES_PER_PT)   // 128

__global__ __launch_bounds__(BLOCK_THREADS)
void rbf_layer_kernel(const float* __restrict__ pos,
                      const float* __restrict__ feat,
                      const float* __restrict__ kern,   // [FOUT][FIN][NB][MB]
                      const int*   __restrict__ nbrs,
                      const int*   __restrict__ rsp,    // row_splits [N+1]
                      float*       __restrict__ out,    // [N][FOUT]
                      int n_pts)
{
    // Shared copy of kernel, transposed to [j][i][n][m] so the epilogue's
    // float4 load at lane-stride 16B is bank-conflict-free.
    __shared__ float sk[FIN * FOUT * NBASIS * MBASIS];  // 1024 floats = 4KB
    for (int idx = threadIdx.x; idx < 1024; idx += blockDim.x) {
        int m = idx & 3;
        int n = (idx >> 2) & 3;
        int i = (idx >> 4) & 7;
        int j = idx >> 7;
        sk[idx] = kern[(((i * FIN + j) * NBASIS + n) * MBASIS) + m];
    }
    __syncthreads();

    int gid   = blockIdx.x * blockDim.x + threadIdx.x;
    int point = gid >> 2;            // 4 lanes per point
    int t     = threadIdx.x & 3;     // owns radial basis n = t
    bool valid = (point < n_pts);
    int pclamp = valid ? point : (n_pts - 1);

    float2 pp = ((const float2*)pos)[pclamp];
    int beg = valid ? rsp[pclamp]     : 0;
    int end = valid ? rsp[pclamp + 1] : 0;

    float Z0[8], Z1[8], Z2[8], Z3[8];
    #pragma unroll
    for (int j = 0; j < 8; ++j) { Z0[j] = Z1[j] = Z2[j] = Z3[j] = 0.0f; }

    const float cen_c  = -1.0f + (float)t * (2.0f / 3.0f);  // radial centroid, n=t
    const float INV_PI = 0.3183098861837907f;
    const float4* f4   = (const float4*)feat;

    for (int e = beg; e < end; ++e) {
        int nb = __ldg(&nbrs[e]);
        float2 q = ((const float2*)pos)[nb];
        float dx = q.x - pp.x;
        float dy = q.y - pp.y;
        float nrm = sqrtf(dx * dx + dy * dy);          // |rel|
        // r = nrm/SUPPORT (SUPPORT=2), x = 2r-1 = nrm-1
        float xc = nrm - 1.0f;
        // radial hat: spacing = 2/3 -> d = |x-cen|*1.5 ; clip(1-d, 0, 1)
        float c = fmaxf(0.0f, 1.0f - fabsf(xc - cen_c) * 1.5f);

        float th = atan2f(dy, dx) * INV_PI;            // in [-1, 1]
        // periodic hats on period 2, spacing 0.5: d = wrap(|x-cen|)*2
        float a0, a1, a2, a3;
        {
            float ra, d;
            ra = th + 1.0f;   d = fabsf(ra - 2.0f * rintf(0.5f * ra));  // cen=-1
            a0 = c * fmaxf(0.0f, 1.0f - 2.0f * d);
            ra = th + 0.5f;   d = fabsf(ra - 2.0f * rintf(0.5f * ra));  // cen=-0.5
            a1 = c * fmaxf(0.0f, 1.0f - 2.0f * d);
            ra = th;          d = fabsf(ra - 2.0f * rintf(0.5f * ra));  // cen=0
            a2 = c * fmaxf(0.0f, 1.0f - 2.0f * d);
            ra = th - 0.5f;   d = fabsf(ra - 2.0f * rintf(0.5f * ra));  // cen=0.5
            a3 = c * fmaxf(0.0f, 1.0f - 2.0f * d);
        }

        float4 g0 = __ldg(&f4[nb * 2 + 0]);
        float4 g1 = __ldg(&f4[nb * 2 + 1]);
        float fv[8] = {g0.x, g0.y, g0.z, g0.w, g1.x, g1.y, g1.z, g1.w};

        #pragma unroll
        for (int j = 0; j < 8; ++j) {
            Z0[j] = fmaf(a0, fv[j], Z0[j]);
            Z1[j] = fmaf(a1, fv[j], Z1[j]);
            Z2[j] = fmaf(a2, fv[j], Z2[j]);
            Z3[j] = fmaf(a3, fv[j], Z3[j]);
        }
    }

    // Epilogue: p[i] = sum_{j} sum_{m} sk[j][i][t][m] * Z_m[j]
    float p[8];
    #pragma unroll
    for (int i = 0; i < 8; ++i) p[i] = 0.0f;

    const float4* sk4 = (const float4*)sk;
    #pragma unroll
    for (int j = 0; j < 8; ++j) {
        float z0 = Z0[j], z1 = Z1[j], z2 = Z2[j], z3 = Z3[j];
        #pragma unroll
        for (int i = 0; i < 8; ++i) {
            float4 kk = sk4[(j * 8 + i) * 4 + t];
            p[i] = fmaf(kk.x, z0, fmaf(kk.y, z1, fmaf(kk.z, z2, fmaf(kk.w, z3, p[i]))));
        }
    }

    // Butterfly reduce across the 4 lanes of this point (lanes aligned to 4).
    #pragma unroll
    for (int i = 0; i < 8; ++i) {
        p[i] += __shfl_xor_sync(0xffffffffu, p[i], 1);
        p[i] += __shfl_xor_sync(0xffffffffu, p[i], 2);
    }

    if (valid) {
        // lane t writes outputs t and t+4 (all lanes hold the full sum)
        float o0 = p[0], o1 = p[4];
        #pragma unroll
        for (int i = 0; i < 4; ++i) {
            if (t == i) { o0 = p[i]; o1 = p[i + 4]; }
        }
        out[point * 8 + t]     = o0;
        out[point * 8 + 4 + t] = o1;
    }
}

extern "C" void kernel_launch(void* const* d_in, const int* in_sizes, int n_in,
                              void* d_out, int out_size)
{
    const float* positions = (const float*)d_in[0];   // [N,2]
    const float* features  = (const float*)d_in[1];   // [N,8]
    const float* kernel    = (const float*)d_in[2];   // [8,8,4,4]
    const int*   neighbors = (const int*)d_in[3];     // [E]
    const int*   row_splits= (const int*)d_in[4];     // [N+1]
    float*       out       = (float*)d_out;           // [N,8]

    int n_pts = in_sizes[0] / 2;
    int blocks = (n_pts + PTS_PER_BLOCK - 1) / PTS_PER_BLOCK;
    rbf_layer_kernel<<<blocks, BLOCK_THREADS>>>(
        positions, features, kernel, neighbors, row_splits, out, n_pts);
}

// round 2
// speedup vs baseline: 1.3288x; 1.3288x over previous
#include <cuda_runtime.h>
#include <math.h>

// rbfLayer, round 2.
// Factorization: Z_p[n,m,j] = sum_{e in p} wr_n(e)*wa_m(e)*feat[nbr_e, j]
//                Out[p,i]   = sum_{n,m,j} K[i,j,n,m] * Z_p[n,m,j]
//
// 4 lanes per point; lane t owns feature pair j = {2t, 2t+1} (f32x2 packed).
// Z = 16 nm slots x 1 f32x2 = 16 u64 regs.
// Geometry (norm + angle) computed once per edge (lane t owns edge g*4+t),
// then (s_r, s_a, nbr) broadcast to the 4-lane group via shfl.
// Hat weights via partition-of-unity: index space s, k=floor(s), fr=s-k;
// weight (1-fr) at k, fr at k+1 (mod nb for angular).

#define PTS_PER_BLOCK 32
#define BLOCK_THREADS 128

typedef unsigned long long u64;

__device__ __forceinline__ u64 pack2(float lo, float hi) {
    u64 r;
    asm("mov.b64 %0, {%1,%2};" : "=l"(r)
        : "r"(__float_as_int(lo)), "r"(__float_as_int(hi)));
    return r;
}
__device__ __forceinline__ void unpack2(u64 v, float& lo, float& hi) {
    int a, b;
    asm("mov.b64 {%0,%1}, %2;" : "=r"(a), "=r"(b) : "l"(v));
    lo = __int_as_float(a); hi = __int_as_float(b);
}
__device__ __forceinline__ u64 fma2(u64 a, u64 b, u64 c) {
    u64 d;
    asm("fma.rn.f32x2 %0, %1, %2, %3;" : "=l"(d) : "l"(a), "l"(b), "l"(c));
    return d;
}
__device__ __forceinline__ u64 mul2(u64 a, u64 b) {
    u64 d;
    asm("mul.rn.f32x2 %0, %1, %2;" : "=l"(d) : "l"(a), "l"(b));
    return d;
}

// norm + angle -> index-space coords (s_r radial, s_a angular)
__device__ __forceinline__ void edge_geom(float dx, float dy,
                                          float& sr, float& sa) {
    float d2 = fmaxf(fmaf(dx, dx, dy * dy), 1e-24f);
    float rinv = rsqrtf(d2);
    float nrm = d2 * rinv;                 // |rel|
    sr = nrm * 1.5f;                       // ((nrm-1)+1)/(2/3)

    // atan2 via octant fold + minimax poly (err ~1e-5 rad)
    float ax = fabsf(dx), ay = fabsf(dy);
    float mn = fminf(ax, ay);
    float mx = fmaxf(fmaxf(ax, ay), 1e-30f);
    float tq = __fdividef(mn, mx);         // in [0,1]
    float t2 = tq * tq;
    float p = -0.0117212f;
    p = fmaf(p, t2, 0.05265332f);
    p = fmaf(p, t2, -0.11643287f);
    p = fmaf(p, t2, 0.19354346f);
    p = fmaf(p, t2, -0.33262347f);
    p = fmaf(p, t2, 0.99997726f);
    float ang = p * tq;
    if (ay > ax) ang = 1.5707963267948966f - ang;
    if (dx < 0.0f) ang = 3.141592653589793f - ang;
    float th = ang * 0.3183098861837907f;  // /pi, in [0,1]
    th = (dy < 0.0f) ? -th : th;           // [-1,1]
    sa = fmaf(th, 2.0f, 2.0f);             // (th+1)*2 in [0,4]
}

// decode PoU weights + accumulate one edge into Z (f32x2 lanes = feature pair)
__device__ __forceinline__ void accum_edge(float sr, float sa, u64 fv2,
                                           u64 Zp[16]) {
    int   kr = (int)sr;          // 0..2 (nrm < 2)
    float fr = sr - (float)kr;
    int   ka = (int)sa;          // 0..4
    float fa = sa - (float)ka;
    int   k0 = ka & 3;
    int   k1 = (ka + 1) & 3;

    float wa0 = (k0 == 0) ? (1.0f - fa) : ((k1 == 0) ? fa : 0.0f);
    float wa1 = (k0 == 1) ? (1.0f - fa) : ((k1 == 1) ? fa : 0.0f);
    float wa2 = (k0 == 2) ? (1.0f - fa) : ((k1 == 2) ? fa : 0.0f);
    float wa3 = (k0 == 3) ? (1.0f - fa) : ((k1 == 3) ? fa : 0.0f);

    float wr0 = (kr == 0) ? (1.0f - fr) : 0.0f;
    float wr1 = (kr == 1) ? (1.0f - fr) : ((kr == 0) ? fr : 0.0f);
    float wr2 = (kr == 2) ? (1.0f - fr) : ((kr == 1) ? fr : 0.0f);
    float wr3 = (kr == 2) ? fr : 0.0f;

    u64 t0 = mul2(pack2(wa0, wa0), fv2);
    u64 t1 = mul2(pack2(wa1, wa1), fv2);
    u64 t2 = mul2(pack2(wa2, wa2), fv2);
    u64 t3 = mul2(pack2(wa3, wa3), fv2);
    u64 r0 = pack2(wr0, wr0);
    u64 r1 = pack2(wr1, wr1);
    u64 r2 = pack2(wr2, wr2);
    u64 r3 = pack2(wr3, wr3);

    Zp[0]  = fma2(r0, t0, Zp[0]);   Zp[1]  = fma2(r0, t1, Zp[1]);
    Zp[2]  = fma2(r0, t2, Zp[2]);   Zp[3]  = fma2(r0, t3, Zp[3]);
    Zp[4]  = fma2(r1, t0, Zp[4]);   Zp[5]  = fma2(r1, t1, Zp[5]);
    Zp[6]  = fma2(r1, t2, Zp[6]);   Zp[7]  = fma2(r1, t3, Zp[7]);
    Zp[8]  = fma2(r2, t0, Zp[8]);   Zp[9]  = fma2(r2, t1, Zp[9]);
    Zp[10] = fma2(r2, t2, Zp[10]);  Zp[11] = fma2(r2, t3, Zp[11]);
    Zp[12] = fma2(r3, t0, Zp[12]);  Zp[13] = fma2(r3, t1, Zp[13]);
    Zp[14] = fma2(r3, t2, Zp[14]);  Zp[15] = fma2(r3, t3, Zp[15]);
}

__global__ __launch_bounds__(BLOCK_THREADS)
void rbf_layer_kernel(const float* __restrict__ pos,
                      const float* __restrict__ feat,
                      const float* __restrict__ kern,   // [8][8][4][4]
                      const int*   __restrict__ nbrs,
                      const int*   __restrict__ rsp,
                      float*       __restrict__ out,
                      int n_pts)
{
    // Shared K packed for the epilogue: skp[i][nm][t] = (K[i][2t][nm], K[i][2t+1][nm])
    __shared__ float2 skp[8 * 16 * 4];     // 4 KB
    for (int idx = threadIdx.x; idx < 512; idx += BLOCK_THREADS) {
        int tt = idx & 3;
        int nm = (idx >> 2) & 15;
        int i  = idx >> 6;
        skp[idx] = make_float2(kern[(i * 8 + 2 * tt)     * 16 + nm],
                               kern[(i * 8 + 2 * tt + 1) * 16 + nm]);
    }
    __syncthreads();

    int gid   = blockIdx.x * BLOCK_THREADS + threadIdx.x;
    int point = gid >> 2;
    int t     = threadIdx.x & 3;
    int lane  = threadIdx.x & 31;
    int base  = lane & ~3;
    unsigned gmask = 0xFu << base;       // the 4-lane group (divergence-safe)

    bool valid = (point < n_pts);
    int pclamp = valid ? point : 0;

    const float2* pos2 = (const float2*)pos;
    const float2* f2   = (const float2*)feat;

    float2 pp = pos2[pclamp];
    int beg = valid ? rsp[pclamp]     : 0;
    int end = valid ? rsp[pclamp + 1] : 0;
    int cnt = end - beg;

    u64 Zp[16];
    #pragma unroll
    for (int k = 0; k < 16; ++k) Zp[k] = 0ull;

    if (cnt == 16) {
        // fast path: lane owns edge g*4+t, geometry shared via shfl
        #pragma unroll
        for (int g = 0; g < 4; ++g) {
            int e  = beg + g * 4 + t;
            int nb = __ldg(nbrs + e);
            float2 q = __ldg(&pos2[nb]);
            float sr, sa;
            edge_geom(q.x - pp.x, q.y - pp.y, sr, sa);
            #pragma unroll
            for (int sub = 0; sub < 4; ++sub) {
                float srs = __shfl_sync(gmask, sr, base + sub);
                float sas = __shfl_sync(gmask, sa, base + sub);
                int   nbs = __shfl_sync(gmask, nb, base + sub);
                float2 fv = __ldg(&f2[nbs * 4 + t]);   // lane's j-pair, 8B coalesced
                accum_edge(srs, sas, pack2(fv.x, fv.y), Zp);
            }
        }
    } else {
        // generic path: all 4 lanes process the same edge (redundant geometry)
        for (int e = beg; e < end; ++e) {
            int nb = __ldg(nbrs + e);
            float2 q = __ldg(&pos2[nb]);
            float sr, sa;
            edge_geom(q.x - pp.x, q.y - pp.y, sr, sa);
            float2 fv = __ldg(&f2[nb * 4 + t]);
            accum_edge(sr, sa, pack2(fv.x, fv.y), Zp);
        }
    }

    // Epilogue: pr[i] = sum_nm <skp[i][nm][t], Zp[nm]> (f32x2), then hadd
    const u64* skp64 = (const u64*)skp;
    float pr[8];
    #pragma unroll
    for (int i = 0; i < 8; ++i) {
        u64 acc = 0ull;
        #pragma unroll
        for (int nm = 0; nm < 16; ++nm)
            acc = fma2(skp64[(i * 16 + nm) * 4 + t], Zp[nm], acc);
        float lo, hi;
        unpack2(acc, lo, hi);
        pr[i] = lo + hi;
    }

    // reduce over the 4 lanes of the point
    #pragma unroll
    for (int i = 0; i < 8; ++i) {
        pr[i] += __shfl_xor_sync(0xffffffffu, pr[i], 1);
        pr[i] += __shfl_xor_sync(0xffffffffu, pr[i], 2);
    }

    if (valid) {
        float o0 = pr[0], o1 = pr[4];
        if (t == 1) { o0 = pr[1]; o1 = pr[5]; }
        if (t == 2) { o0 = pr[2]; o1 = pr[6]; }
        if (t == 3) { o0 = pr[3]; o1 = pr[7]; }
        out[point * 8 + t]     = o0;
        out[point * 8 + 4 + t] = o1;
    }
}

extern "C" void kernel_launch(void* const* d_in, const int* in_sizes, int n_in,
                              void* d_out, int out_size)
{
    const float* positions  = (const float*)d_in[0];
    const float* features   = (const float*)d_in[1];
    const float* kernel     = (const float*)d_in[2];
    const int*   neighbors  = (const int*)d_in[3];
    const int*   row_splits = (const int*)d_in[4];
    float*       out        = (float*)d_out;

    int n_pts = in_sizes[0] / 2;
    int blocks = (n_pts + PTS_PER_BLOCK - 1) / PTS_PER_BLOCK;
    rbf_layer_kernel<<<blocks, BLOCK_THREADS>>>(
        positions, features, kernel, neighbors, row_splits, out, n_pts);
}